// round 1
// baseline (speedup 1.0000x reference)
#include <cuda_runtime.h>
#include <math.h>

// ---------------- Problem constants ----------------
#define LSEQ   2048
#define DMODEL 4096
#define NH     128          // heads
#define DP     64           // head dim
#define NG     8            // groups
#define DN     128          // state dim
#define CSZ    128          // chunk size
#define NCH    (LSEQ / CSZ) // 16 chunks
#define KCONV  4
#define DINTER 8192         // NH*DP
#define DCONV  10240        // DINTER + 2*NG*DN
#define DPROJ  18560        // DINTER + DCONV + NH
#define RMS_EPS 1e-5f

// ---------------- Scratch (device globals; no cudaMalloc allowed) ----------------
__device__ float g_proj[LSEQ * DPROJ];            // in-proj output (gate | hBC | dt)
__device__ float g_xbc[LSEQ * DCONV];             // conv+silu output (x | B | C)
__device__ float g_dt[LSEQ * NH];                 // softplus(dt + bias)
__device__ float g_acs[NCH * NH * CSZ];           // per-chunk inclusive cumsum of A*dt
__device__ float g_alast[NCH * NH];               // chunk totals
__device__ float g_cbt[NCH * NG * CSZ * CSZ];     // CBt[c][g][s][l] = sum_n C[l,n]*B[s,n]
__device__ float g_states[NCH * NH * DP * DN];    // per-chunk local states
__device__ float g_prefix[NCH * NH * DP * DN];    // state entering each chunk
__device__ float g_y[LSEQ * DINTER];              // y (then gated/normed in place)

// ---------------- GEMM: C[M,Nd] = A[M,Kd] * B[Nd,Kd]^T  (all row-major, fp32) ----------------
// BM=128, BN=64, BK=16, 256 threads, 8x4 per thread. Dims assumed divisible.
__global__ __launch_bounds__(256) void gemm_nt_kernel(
    const float* __restrict__ A, const float* __restrict__ B, float* __restrict__ C,
    int Nd, int Kd)
{
    __shared__ float As[16][128];
    __shared__ float Bs[16][64];
    const int tid = threadIdx.x;
    const int tx = tid & 15, ty = tid >> 4;
    const int bm = blockIdx.y * 128, bn = blockIdx.x * 64;

    float acc[8][4];
#pragma unroll
    for (int i = 0; i < 8; i++)
#pragma unroll
        for (int j = 0; j < 4; j++) acc[i][j] = 0.f;

    const int lin = tid * 4;
    const int ai0 = lin >> 4;          // 0..63
    const int ak  = lin & 15;          // 0,4,8,12
    const int ai1 = ai0 + 64;
    const float* Arow0 = A + (size_t)(bm + ai0) * Kd + ak;
    const float* Arow1 = A + (size_t)(bm + ai1) * Kd + ak;
    const float* Brow  = B + (size_t)(bn + ai0) * Kd + ak;

    for (int k0 = 0; k0 < Kd; k0 += 16) {
        float4 va0 = *(const float4*)(Arow0 + k0);
        float4 va1 = *(const float4*)(Arow1 + k0);
        float4 vb  = *(const float4*)(Brow  + k0);
        As[ak + 0][ai0] = va0.x; As[ak + 1][ai0] = va0.y;
        As[ak + 2][ai0] = va0.z; As[ak + 3][ai0] = va0.w;
        As[ak + 0][ai1] = va1.x; As[ak + 1][ai1] = va1.y;
        As[ak + 2][ai1] = va1.z; As[ak + 3][ai1] = va1.w;
        Bs[ak + 0][ai0] = vb.x;  Bs[ak + 1][ai0] = vb.y;
        Bs[ak + 2][ai0] = vb.z;  Bs[ak + 3][ai0] = vb.w;
        __syncthreads();
#pragma unroll
        for (int kk = 0; kk < 16; kk++) {
            float4 a0 = *(const float4*)&As[kk][ty * 8];
            float4 a1 = *(const float4*)&As[kk][ty * 8 + 4];
            float4 b  = *(const float4*)&Bs[kk][tx * 4];
            float aa[8] = {a0.x, a0.y, a0.z, a0.w, a1.x, a1.y, a1.z, a1.w};
            float bb[4] = {b.x, b.y, b.z, b.w};
#pragma unroll
            for (int i = 0; i < 8; i++)
#pragma unroll
                for (int j = 0; j < 4; j++) acc[i][j] += aa[i] * bb[j];
        }
        __syncthreads();
    }
#pragma unroll
    for (int i = 0; i < 8; i++) {
        float4 v = make_float4(acc[i][0], acc[i][1], acc[i][2], acc[i][3]);
        *(float4*)(C + (size_t)(bm + ty * 8 + i) * Nd + bn + tx * 4) = v;
    }
}

// ---------------- Depthwise causal conv (K=4) + SiLU over proj[:, DINTER:DINTER+DCONV] ----------------
__global__ void conv_silu_kernel(const float* __restrict__ conv_w, const float* __restrict__ conv_b)
{
    int idx = blockIdx.x * blockDim.x + threadIdx.x;
    if (idx >= LSEQ * DCONV) return;
    int t = idx / DCONV, c = idx % DCONV;
    float acc = conv_b[c];
    const float* w = conv_w + c * KCONV;
#pragma unroll
    for (int k = 0; k < KCONV; k++) {
        int tt = t + k - (KCONV - 1);
        if (tt >= 0) acc += w[k] * g_proj[(size_t)tt * DPROJ + DINTER + c];
    }
    g_xbc[idx] = acc / (1.f + __expf(-acc));
}

// ---------------- dt softplus + per-chunk cumsum of A*dt ----------------
__global__ __launch_bounds__(CSZ) void dt_scan_kernel(
    const float* __restrict__ dt_bias, const float* __restrict__ A_log)
{
    int c = blockIdx.x, h = blockIdx.y, l = threadIdx.x;
    int t = c * CSZ + l;
    float raw = g_proj[(size_t)t * DPROJ + DINTER + DCONV + h] + dt_bias[h];
    float dtp = (raw > 0.f) ? (raw + log1pf(__expf(-raw))) : log1pf(__expf(raw));
    g_dt[t * NH + h] = dtp;
    float a = -__expf(A_log[h]) * dtp;

    __shared__ float s[CSZ];
    s[l] = a;
    __syncthreads();
#pragma unroll
    for (int off = 1; off < CSZ; off <<= 1) {
        float v = (l >= off) ? s[l - off] : 0.f;
        __syncthreads();
        s[l] += v;
        __syncthreads();
    }
    g_acs[(c * NH + h) * CSZ + l] = s[l];
    if (l == CSZ - 1) g_alast[c * NH + h] = s[l];
}

// ---------------- CBt[c][g][s][l] = sum_n C[l,n]*B[s,n] ----------------
__global__ __launch_bounds__(256) void cb_kernel()
{
    int c = blockIdx.x, g = blockIdx.y;
    int tid = threadIdx.x, tx = tid & 15, ty = tid >> 4; // l = tx*8+li, s = ty*8+si
    __shared__ float Csn[16][CSZ];
    __shared__ float Bsn[16][CSZ];
    float acc[8][8];
#pragma unroll
    for (int i = 0; i < 8; i++)
#pragma unroll
        for (int j = 0; j < 8; j++) acc[i][j] = 0.f;

    const float* Cg = g_xbc + DINTER + NG * DN + g * DN;
    const float* Bg = g_xbc + DINTER + g * DN;

    for (int n0 = 0; n0 < DN; n0 += 16) {
        for (int i = tid; i < CSZ * 4; i += 256) {
            int r = i >> 2, q = i & 3;
            const size_t row = (size_t)(c * CSZ + r) * DCONV + n0 + q * 4;
            float4 cv = *(const float4*)(Cg + row);
            float4 bv = *(const float4*)(Bg + row);
            Csn[q * 4 + 0][r] = cv.x; Csn[q * 4 + 1][r] = cv.y;
            Csn[q * 4 + 2][r] = cv.z; Csn[q * 4 + 3][r] = cv.w;
            Bsn[q * 4 + 0][r] = bv.x; Bsn[q * 4 + 1][r] = bv.y;
            Bsn[q * 4 + 2][r] = bv.z; Bsn[q * 4 + 3][r] = bv.w;
        }
        __syncthreads();
#pragma unroll
        for (int nn = 0; nn < 16; nn++) {
            float4 c0 = *(const float4*)&Csn[nn][tx * 8];
            float4 c1 = *(const float4*)&Csn[nn][tx * 8 + 4];
            float4 b0 = *(const float4*)&Bsn[nn][ty * 8];
            float4 b1 = *(const float4*)&Bsn[nn][ty * 8 + 4];
            float cl[8] = {c0.x, c0.y, c0.z, c0.w, c1.x, c1.y, c1.z, c1.w};
            float bs[8] = {b0.x, b0.y, b0.z, b0.w, b1.x, b1.y, b1.z, b1.w};
#pragma unroll
            for (int si = 0; si < 8; si++)
#pragma unroll
                for (int li = 0; li < 8; li++) acc[si][li] += cl[li] * bs[si];
        }
        __syncthreads();
    }
    float* out = g_cbt + (size_t)(c * NG + g) * CSZ * CSZ;
#pragma unroll
    for (int si = 0; si < 8; si++) {
        int s = ty * 8 + si;
        *(float4*)(out + (size_t)s * CSZ + tx * 8)     = make_float4(acc[si][0], acc[si][1], acc[si][2], acc[si][3]);
        *(float4*)(out + (size_t)s * CSZ + tx * 8 + 4) = make_float4(acc[si][4], acc[si][5], acc[si][6], acc[si][7]);
    }
}

// ---------------- Y_diag + D residual: one CTA per (chunk, head) ----------------
__global__ __launch_bounds__(256) void ydiag_kernel(const float* __restrict__ Dparam)
{
    int c = blockIdx.x, h = blockIdx.y, g = h >> 4;
    int tid = threadIdx.x, tx = tid & 15, ty = tid >> 4; // l = ty*8+i, p = tx*4+j
    __shared__ float xs[CSZ][DP];   // raw x
    __shared__ float acsS[CSZ];
    __shared__ float dts[CSZ];

    for (int i = tid; i < CSZ * DP / 4; i += 256) {
        int r = i >> 4, q = i & 15;
        *(float4*)&xs[r][q * 4] =
            *(const float4*)(g_xbc + (size_t)(c * CSZ + r) * DCONV + h * DP + q * 4);
    }
    if (tid < CSZ) {
        dts[tid]  = g_dt[(c * CSZ + tid) * NH + h];
        acsS[tid] = g_acs[(c * NH + h) * CSZ + tid];
    }
    __syncthreads();

    float acs_l[8];
#pragma unroll
    for (int i = 0; i < 8; i++) acs_l[i] = acsS[ty * 8 + i];

    float acc[8][4];
#pragma unroll
    for (int i = 0; i < 8; i++)
#pragma unroll
        for (int j = 0; j < 4; j++) acc[i][j] = 0.f;

    const float* cbBase = g_cbt + (size_t)(c * NG + g) * CSZ * CSZ;
    const int lmax = ty * 8 + 7;
    for (int s = 0; s <= lmax; s++) {
        float av  = acsS[s];
        float dsv = dts[s];
        float4 cb0 = *(const float4*)(cbBase + (size_t)s * CSZ + ty * 8);
        float4 cb1 = *(const float4*)(cbBase + (size_t)s * CSZ + ty * 8 + 4);
        float cb[8] = {cb0.x, cb0.y, cb0.z, cb0.w, cb1.x, cb1.y, cb1.z, cb1.w};
        float4 xv4 = *(const float4*)&xs[s][tx * 4];
        float xv[4] = {xv4.x, xv4.y, xv4.z, xv4.w};
#pragma unroll
        for (int i = 0; i < 8; i++) {
            int l = ty * 8 + i;
            float f = 0.f;
            if (s <= l) f = cb[i] * __expf(fminf(acs_l[i] - av, 0.f)) * dsv;
#pragma unroll
            for (int j = 0; j < 4; j++) acc[i][j] += f * xv[j];
        }
    }
    const float dcoef = Dparam[h];
#pragma unroll
    for (int i = 0; i < 8; i++) {
        int l = ty * 8 + i;
        float4 xr = *(const float4*)&xs[l][tx * 4];
        float4 o = make_float4(acc[i][0] + dcoef * xr.x, acc[i][1] + dcoef * xr.y,
                               acc[i][2] + dcoef * xr.z, acc[i][3] + dcoef * xr.w);
        *(float4*)(g_y + (size_t)(c * CSZ + l) * DINTER + h * DP + tx * 4) = o;
    }
}

// ---------------- Local chunk states: states[c,h,p,n] = sum_l B[l,n]*exp(alast-acs[l])*dt[l]*x[l,p] ----------------
__global__ __launch_bounds__(256) void states_kernel()
{
    int c = blockIdx.x, h = blockIdx.y, g = h >> 4;
    int tid = threadIdx.x, tx = tid & 15, ty = tid >> 4; // n = tx*8+nj, p = ty*4+pi
    __shared__ float Bsh[32][DN];
    __shared__ float xds[32][DP];
    __shared__ float dec[32];
    float acc[4][8];
#pragma unroll
    for (int i = 0; i < 4; i++)
#pragma unroll
        for (int j = 0; j < 8; j++) acc[i][j] = 0.f;

    const float al = g_alast[c * NH + h];
    for (int l0 = 0; l0 < CSZ; l0 += 32) {
        for (int i = tid; i < 32 * DN / 4; i += 256) {
            int r = i >> 5, q = i & 31;
            *(float4*)&Bsh[r][q * 4] = *(const float4*)(
                g_xbc + (size_t)(c * CSZ + l0 + r) * DCONV + DINTER + g * DN + q * 4);
        }
        for (int i = tid; i < 32 * DP / 4; i += 256) {
            int r = i >> 4, q = i & 15;
            int t = c * CSZ + l0 + r;
            float4 xv = *(const float4*)(g_xbc + (size_t)t * DCONV + h * DP + q * 4);
            float d = g_dt[t * NH + h];
            xv.x *= d; xv.y *= d; xv.z *= d; xv.w *= d;
            *(float4*)&xds[r][q * 4] = xv;
        }
        if (tid < 32) dec[tid] = __expf(al - g_acs[(c * NH + h) * CSZ + l0 + tid]);
        __syncthreads();
#pragma unroll 8
        for (int ll = 0; ll < 32; ll++) {
            float d = dec[ll];
            float4 b0 = *(const float4*)&Bsh[ll][tx * 8];
            float4 b1 = *(const float4*)&Bsh[ll][tx * 8 + 4];
            float bb[8] = {b0.x, b0.y, b0.z, b0.w, b1.x, b1.y, b1.z, b1.w};
            float4 xv = *(const float4*)&xds[ll][ty * 4];
            float xp[4] = {xv.x * d, xv.y * d, xv.z * d, xv.w * d};
#pragma unroll
            for (int pi = 0; pi < 4; pi++)
#pragma unroll
                for (int nj = 0; nj < 8; nj++) acc[pi][nj] += xp[pi] * bb[nj];
        }
        __syncthreads();
    }
    float* out = g_states + (size_t)(c * NH + h) * DP * DN;
#pragma unroll
    for (int pi = 0; pi < 4; pi++) {
        int p = ty * 4 + pi;
        *(float4*)(out + (size_t)p * DN + tx * 8)     = make_float4(acc[pi][0], acc[pi][1], acc[pi][2], acc[pi][3]);
        *(float4*)(out + (size_t)p * DN + tx * 8 + 4) = make_float4(acc[pi][4], acc[pi][5], acc[pi][6], acc[pi][7]);
    }
}

// ---------------- Inter-chunk scan: prefix[c] = state entering chunk c ----------------
__global__ void prefix_kernel()
{
    int idx = blockIdx.x * blockDim.x + threadIdx.x;
    if (idx >= NH * DP * DN) return;
    int h = idx >> 13; // / (DP*DN)
    float s = 0.f;
#pragma unroll
    for (int c = 0; c < NCH; c++) {
        size_t off = (size_t)c * NH * DP * DN + idx;
        g_prefix[off] = s;
        s = __expf(g_alast[c * NH + h]) * s + g_states[off];
    }
}

// ---------------- Y_off: y += exp(acs[l]) * sum_n C[l,n]*prefix[c,h,p,n] ----------------
__global__ __launch_bounds__(256) void yoff_kernel()
{
    int c = blockIdx.x, h = blockIdx.y, g = h >> 4;
    int tid = threadIdx.x, tx = tid & 15, ty = tid >> 4; // l = ty*8+i, p = tx*4+j
    __shared__ float Cs[CSZ][32];
    __shared__ float Pf[DP][33];
    __shared__ float acsS[CSZ];
    if (tid < CSZ) acsS[tid] = g_acs[(c * NH + h) * CSZ + tid];

    float acc[8][4];
#pragma unroll
    for (int i = 0; i < 8; i++)
#pragma unroll
        for (int j = 0; j < 4; j++) acc[i][j] = 0.f;

    for (int n0 = 0; n0 < DN; n0 += 32) {
        for (int i = tid; i < CSZ * 8; i += 256) {
            int r = i >> 3, q = i & 7;
            *(float4*)&Cs[r][q * 4] = *(const float4*)(
                g_xbc + (size_t)(c * CSZ + r) * DCONV + DINTER + NG * DN + g * DN + n0 + q * 4);
        }
        for (int i = tid; i < DP * 8; i += 256) {
            int r = i >> 3, q = i & 7;
            float4 v = *(const float4*)(
                g_prefix + ((size_t)(c * NH + h) * DP + r) * DN + n0 + q * 4);
            Pf[r][q * 4 + 0] = v.x; Pf[r][q * 4 + 1] = v.y;
            Pf[r][q * 4 + 2] = v.z; Pf[r][q * 4 + 3] = v.w;
        }
        __syncthreads();
#pragma unroll 8
        for (int nn = 0; nn < 32; nn++) {
            float cl[8], pv[4];
#pragma unroll
            for (int i = 0; i < 8; i++) cl[i] = Cs[ty * 8 + i][nn];
#pragma unroll
            for (int j = 0; j < 4; j++) pv[j] = Pf[tx * 4 + j][nn];
#pragma unroll
            for (int i = 0; i < 8; i++)
#pragma unroll
                for (int j = 0; j < 4; j++) acc[i][j] += cl[i] * pv[j];
        }
        __syncthreads();
    }
#pragma unroll
    for (int i = 0; i < 8; i++) {
        int l = ty * 8 + i;
        float e = __expf(acsS[l]);
        float* yp = g_y + (size_t)(c * CSZ + l) * DINTER + h * DP + tx * 4;
        float4 y = *(float4*)yp;
        y.x += e * acc[i][0]; y.y += e * acc[i][1];
        y.z += e * acc[i][2]; y.w += e * acc[i][3];
        *(float4*)yp = y;
    }
}

// ---------------- RMSNorm * norm_w * silu(gate), in place on g_y ----------------
__global__ __launch_bounds__(256) void rms_gate_kernel(const float* __restrict__ norm_w)
{
    int t = blockIdx.x, tid = threadIdx.x;
    const size_t base = (size_t)t * DINTER;
    float ss = 0.f;
    for (int i = tid; i < DINTER; i += 256) {
        float v = g_y[base + i];
        ss += v * v;
    }
    __shared__ float red[256];
    red[tid] = ss;
    __syncthreads();
#pragma unroll
    for (int o = 128; o > 0; o >>= 1) {
        if (tid < o) red[tid] += red[tid + o];
        __syncthreads();
    }
    float inv = rsqrtf(red[0] / (float)DINTER + RMS_EPS);
    for (int i = tid; i < DINTER; i += 256) {
        float v = g_y[base + i] * inv * norm_w[i];
        float gt = g_proj[(size_t)t * DPROJ + i];
        v *= gt / (1.f + __expf(-gt));
        g_y[base + i] = v;
    }
}

// ---------------- Launch ----------------
extern "C" void kernel_launch(void* const* d_in, const int* in_sizes, int n_in,
                              void* d_out, int out_size)
{
    (void)in_sizes; (void)n_in; (void)out_size;
    const float* hs         = (const float*)d_in[0];
    const float* in_proj_w  = (const float*)d_in[1];
    const float* conv_w     = (const float*)d_in[2];
    const float* conv_b     = (const float*)d_in[3];
    const float* dt_bias    = (const float*)d_in[4];
    const float* A_log      = (const float*)d_in[5];
    const float* Dp         = (const float*)d_in[6];
    const float* norm_w     = (const float*)d_in[7];
    const float* out_proj_w = (const float*)d_in[8];
    float* out = (float*)d_out;

    void *p_proj = nullptr, *p_y = nullptr;
    cudaGetSymbolAddress(&p_proj, g_proj);
    cudaGetSymbolAddress(&p_y, g_y);

    // 1) in-proj GEMM: (2048 x 18560) = hs (2048 x 4096) @ W^T
    gemm_nt_kernel<<<dim3(DPROJ / 64, LSEQ / 128), 256>>>(hs, in_proj_w, (float*)p_proj, DPROJ, DMODEL);
    // 2) causal depthwise conv + silu
    conv_silu_kernel<<<(LSEQ * DCONV + 255) / 256, 256>>>(conv_w, conv_b);
    // 3) dt softplus + per-chunk cumsum of A*dt
    dt_scan_kernel<<<dim3(NCH, NH), CSZ>>>(dt_bias, A_log);
    // 4) C·B^T per (chunk, group)
    cb_kernel<<<dim3(NCH, NG), 256>>>();
    // 5) intra-chunk (diagonal) output + D residual
    ydiag_kernel<<<dim3(NCH, NH), 256>>>(Dp);
    // 6) local chunk states
    states_kernel<<<dim3(NCH, NH), 256>>>();
    // 7) inter-chunk state scan
    prefix_kernel<<<(NH * DP * DN + 255) / 256, 256>>>();
    // 8) off-diagonal output (adds into g_y)
    yoff_kernel<<<dim3(NCH, NH), 256>>>();
    // 9) gated RMSNorm (in place)
    rms_gate_kernel<<<LSEQ, 256>>>(norm_w);
    // 10) out-proj GEMM: (2048 x 4096) = y (2048 x 8192) @ W^T
    gemm_nt_kernel<<<dim3(DMODEL / 64, LSEQ / 128), 256>>>((const float*)p_y, out_proj_w, out, DMODEL, DINTER);
}

// round 2
// speedup vs baseline: 2.4550x; 2.4550x over previous
#include <cuda_runtime.h>
#include <math.h>
#include <stdint.h>

// ---------------- Problem constants ----------------
#define LSEQ   2048
#define DMODEL 4096
#define NH     128          // heads
#define DP     64           // head dim
#define NG     8            // groups
#define DN     128          // state dim
#define CSZ    128          // chunk size
#define NCH    (LSEQ / CSZ) // 16 chunks
#define KCONV  4
#define DINTER 8192         // NH*DP
#define DCONV  10240        // DINTER + 2*NG*DN
#define DPROJ  18560        // DINTER + DCONV + NH
#define RMS_EPS 1e-5f

// ---------------- Scratch (device globals; no cudaMalloc allowed) ----------------
__device__ float g_proj[LSEQ * DPROJ];            // in-proj output (gate | hBC | dt)
__device__ float g_xbc[LSEQ * DCONV];             // conv+silu output (x | B | C)
__device__ float g_dt[LSEQ * NH];                 // softplus(dt + bias)
__device__ float g_acs[NCH * NH * CSZ];           // per-chunk inclusive cumsum of A*dt
__device__ float g_alast[NCH * NH];               // chunk totals
__device__ float g_cbt[NCH * NG * CSZ * CSZ];     // CBt[c][g][s][l]
__device__ float g_states[NCH * NH * DP * DN];    // per-chunk local states
__device__ float g_prefix[NCH * NH * DP * DN];    // state entering each chunk
__device__ float g_y[LSEQ * DINTER];              // y (then gated/normed in place)

// ---------------- tf32 helpers ----------------
__device__ __forceinline__ uint32_t f2tf32(float f) {
    uint32_t r;
    asm("cvt.rna.tf32.f32 %0, %1;" : "=r"(r) : "f"(f));
    return r;
}

__device__ __forceinline__ void mma_tf32(float c[4], const uint32_t a[4], const uint32_t b[2]) {
    asm volatile(
        "mma.sync.aligned.m16n8k8.row.col.f32.tf32.tf32.f32 "
        "{%0,%1,%2,%3}, {%4,%5,%6,%7}, {%8,%9}, {%0,%1,%2,%3};"
        : "+f"(c[0]), "+f"(c[1]), "+f"(c[2]), "+f"(c[3])
        : "r"(a[0]), "r"(a[1]), "r"(a[2]), "r"(a[3]), "r"(b[0]), "r"(b[1]));
}

// ---------------- tf32 GEMM: C[M,Nd] = A[M,Kd] * B[Nd,Kd]^T (row-major) ----------------
// BM=128, BN=128, BK=16, 256 threads (8 warps), warp tile 64x32, double-buffered smem.
// Smem row stride 20 (pad 4): conflict-free fragment loads, aligned float4 staging.
__global__ __launch_bounds__(256) void gemm_tf32_kernel(
    const float* __restrict__ A, const float* __restrict__ B, float* __restrict__ C,
    int Nd, int Kd)
{
    __shared__ uint32_t As[2][128][20];
    __shared__ uint32_t Bs[2][128][20];

    const int tid  = threadIdx.x;
    const int lane = tid & 31, warp = tid >> 5;
    const int wm = (warp >> 2) * 64;   // warp m offset within CTA tile
    const int wn = (warp & 3) * 32;    // warp n offset
    const int g  = lane >> 2, tq = lane & 3;
    const int bm = blockIdx.y * 128, bn = blockIdx.x * 128;

    // staging indices: each thread loads 2 float4 of A and 2 of B per tile
    const int r0 = tid >> 2, c4 = (tid & 3) * 4;       // rows 0..63
    const int r1 = r0 + 64;
    const float* Ag0 = A + (size_t)(bm + r0) * Kd + c4;
    const float* Ag1 = A + (size_t)(bm + r1) * Kd + c4;
    const float* Bg0 = B + (size_t)(bn + r0) * Kd + c4;
    const float* Bg1 = B + (size_t)(bn + r1) * Kd + c4;

    float acc[4][4][4];
#pragma unroll
    for (int mt = 0; mt < 4; mt++)
#pragma unroll
        for (int nt = 0; nt < 4; nt++)
#pragma unroll
            for (int q = 0; q < 4; q++) acc[mt][nt][q] = 0.f;

    // preload tile 0
    {
        float4 a0 = *(const float4*)(Ag0);
        float4 a1 = *(const float4*)(Ag1);
        float4 b0 = *(const float4*)(Bg0);
        float4 b1 = *(const float4*)(Bg1);
        As[0][r0][c4+0]=f2tf32(a0.x); As[0][r0][c4+1]=f2tf32(a0.y); As[0][r0][c4+2]=f2tf32(a0.z); As[0][r0][c4+3]=f2tf32(a0.w);
        As[0][r1][c4+0]=f2tf32(a1.x); As[0][r1][c4+1]=f2tf32(a1.y); As[0][r1][c4+2]=f2tf32(a1.z); As[0][r1][c4+3]=f2tf32(a1.w);
        Bs[0][r0][c4+0]=f2tf32(b0.x); Bs[0][r0][c4+1]=f2tf32(b0.y); Bs[0][r0][c4+2]=f2tf32(b0.z); Bs[0][r0][c4+3]=f2tf32(b0.w);
        Bs[0][r1][c4+0]=f2tf32(b1.x); Bs[0][r1][c4+1]=f2tf32(b1.y); Bs[0][r1][c4+2]=f2tf32(b1.z); Bs[0][r1][c4+3]=f2tf32(b1.w);
    }
    __syncthreads();

    const int KT = Kd >> 4;
    int cur = 0;
    for (int kt = 0; kt < KT; kt++) {
        float4 na0, na1, nb0, nb1;
        const bool has_next = (kt + 1 < KT);
        if (has_next) {
            int ko = (kt + 1) << 4;
            na0 = *(const float4*)(Ag0 + ko);
            na1 = *(const float4*)(Ag1 + ko);
            nb0 = *(const float4*)(Bg0 + ko);
            nb1 = *(const float4*)(Bg1 + ko);
        }

#pragma unroll
        for (int ks = 0; ks < 2; ks++) {
            const int ko = ks * 8;
            uint32_t af[4][4], bf[4][2];
#pragma unroll
            for (int mt = 0; mt < 4; mt++) {
                const int m0 = wm + mt * 16;
                af[mt][0] = As[cur][m0 + g    ][ko + tq];
                af[mt][1] = As[cur][m0 + g + 8][ko + tq];
                af[mt][2] = As[cur][m0 + g    ][ko + tq + 4];
                af[mt][3] = As[cur][m0 + g + 8][ko + tq + 4];
            }
#pragma unroll
            for (int nt = 0; nt < 4; nt++) {
                const int n0 = wn + nt * 8;
                bf[nt][0] = Bs[cur][n0 + g][ko + tq];
                bf[nt][1] = Bs[cur][n0 + g][ko + tq + 4];
            }
#pragma unroll
            for (int mt = 0; mt < 4; mt++)
#pragma unroll
                for (int nt = 0; nt < 4; nt++)
                    mma_tf32(acc[mt][nt], af[mt], bf[nt]);
        }

        if (has_next) {
            int nxt = cur ^ 1;
            As[nxt][r0][c4+0]=f2tf32(na0.x); As[nxt][r0][c4+1]=f2tf32(na0.y); As[nxt][r0][c4+2]=f2tf32(na0.z); As[nxt][r0][c4+3]=f2tf32(na0.w);
            As[nxt][r1][c4+0]=f2tf32(na1.x); As[nxt][r1][c4+1]=f2tf32(na1.y); As[nxt][r1][c4+2]=f2tf32(na1.z); As[nxt][r1][c4+3]=f2tf32(na1.w);
            Bs[nxt][r0][c4+0]=f2tf32(nb0.x); Bs[nxt][r0][c4+1]=f2tf32(nb0.y); Bs[nxt][r0][c4+2]=f2tf32(nb0.z); Bs[nxt][r0][c4+3]=f2tf32(nb0.w);
            Bs[nxt][r1][c4+0]=f2tf32(nb1.x); Bs[nxt][r1][c4+1]=f2tf32(nb1.y); Bs[nxt][r1][c4+2]=f2tf32(nb1.z); Bs[nxt][r1][c4+3]=f2tf32(nb1.w);
            cur = nxt;
        }
        __syncthreads();
    }

    // epilogue: c0/c1 at (row, 2*tq), (row, 2*tq+1); c2/c3 at row+8
#pragma unroll
    for (int mt = 0; mt < 4; mt++) {
#pragma unroll
        for (int nt = 0; nt < 4; nt++) {
            const int row = bm + wm + mt * 16 + g;
            const int col = bn + wn + nt * 8 + 2 * tq;
            *(float2*)&C[(size_t)row * Nd + col]       = make_float2(acc[mt][nt][0], acc[mt][nt][1]);
            *(float2*)&C[(size_t)(row + 8) * Nd + col] = make_float2(acc[mt][nt][2], acc[mt][nt][3]);
        }
    }
}

// ---------------- Depthwise causal conv (K=4) + SiLU ----------------
__global__ void conv_silu_kernel(const float* __restrict__ conv_w, const float* __restrict__ conv_b)
{
    int idx = blockIdx.x * blockDim.x + threadIdx.x;
    if (idx >= LSEQ * DCONV) return;
    int t = idx / DCONV, c = idx % DCONV;
    float acc = conv_b[c];
    const float* w = conv_w + c * KCONV;
#pragma unroll
    for (int k = 0; k < KCONV; k++) {
        int tt = t + k - (KCONV - 1);
        if (tt >= 0) acc += w[k] * g_proj[(size_t)tt * DPROJ + DINTER + c];
    }
    g_xbc[idx] = acc / (1.f + __expf(-acc));
}

// ---------------- dt softplus + per-chunk cumsum of A*dt ----------------
__global__ __launch_bounds__(CSZ) void dt_scan_kernel(
    const float* __restrict__ dt_bias, const float* __restrict__ A_log)
{
    int c = blockIdx.x, h = blockIdx.y, l = threadIdx.x;
    int t = c * CSZ + l;
    float raw = g_proj[(size_t)t * DPROJ + DINTER + DCONV + h] + dt_bias[h];
    float dtp = (raw > 0.f) ? (raw + log1pf(__expf(-raw))) : log1pf(__expf(raw));
    g_dt[t * NH + h] = dtp;
    float a = -__expf(A_log[h]) * dtp;

    __shared__ float s[CSZ];
    s[l] = a;
    __syncthreads();
#pragma unroll
    for (int off = 1; off < CSZ; off <<= 1) {
        float v = (l >= off) ? s[l - off] : 0.f;
        __syncthreads();
        s[l] += v;
        __syncthreads();
    }
    g_acs[(c * NH + h) * CSZ + l] = s[l];
    if (l == CSZ - 1) g_alast[c * NH + h] = s[l];
}

// ---------------- CBt[c][g][s][l] = sum_n C[l,n]*B[s,n] ----------------
__global__ __launch_bounds__(256) void cb_kernel()
{
    int c = blockIdx.x, g = blockIdx.y;
    int tid = threadIdx.x, tx = tid & 15, ty = tid >> 4;
    __shared__ float Csn[16][CSZ];
    __shared__ float Bsn[16][CSZ];
    float acc[8][8];
#pragma unroll
    for (int i = 0; i < 8; i++)
#pragma unroll
        for (int j = 0; j < 8; j++) acc[i][j] = 0.f;

    const float* Cg = g_xbc + DINTER + NG * DN + g * DN;
    const float* Bg = g_xbc + DINTER + g * DN;

    for (int n0 = 0; n0 < DN; n0 += 16) {
        for (int i = tid; i < CSZ * 4; i += 256) {
            int r = i >> 2, q = i & 3;
            const size_t row = (size_t)(c * CSZ + r) * DCONV + n0 + q * 4;
            float4 cv = *(const float4*)(Cg + row);
            float4 bv = *(const float4*)(Bg + row);
            Csn[q * 4 + 0][r] = cv.x; Csn[q * 4 + 1][r] = cv.y;
            Csn[q * 4 + 2][r] = cv.z; Csn[q * 4 + 3][r] = cv.w;
            Bsn[q * 4 + 0][r] = bv.x; Bsn[q * 4 + 1][r] = bv.y;
            Bsn[q * 4 + 2][r] = bv.z; Bsn[q * 4 + 3][r] = bv.w;
        }
        __syncthreads();
#pragma unroll
        for (int nn = 0; nn < 16; nn++) {
            float4 c0 = *(const float4*)&Csn[nn][tx * 8];
            float4 c1 = *(const float4*)&Csn[nn][tx * 8 + 4];
            float4 b0 = *(const float4*)&Bsn[nn][ty * 8];
            float4 b1 = *(const float4*)&Bsn[nn][ty * 8 + 4];
            float cl[8] = {c0.x, c0.y, c0.z, c0.w, c1.x, c1.y, c1.z, c1.w};
            float bs[8] = {b0.x, b0.y, b0.z, b0.w, b1.x, b1.y, b1.z, b1.w};
#pragma unroll
            for (int si = 0; si < 8; si++)
#pragma unroll
                for (int li = 0; li < 8; li++) acc[si][li] += cl[li] * bs[si];
        }
        __syncthreads();
    }
    float* out = g_cbt + (size_t)(c * NG + g) * CSZ * CSZ;
#pragma unroll
    for (int si = 0; si < 8; si++) {
        int s = ty * 8 + si;
        *(float4*)(out + (size_t)s * CSZ + tx * 8)     = make_float4(acc[si][0], acc[si][1], acc[si][2], acc[si][3]);
        *(float4*)(out + (size_t)s * CSZ + tx * 8 + 4) = make_float4(acc[si][4], acc[si][5], acc[si][6], acc[si][7]);
    }
}

// ---------------- Y_diag + D residual ----------------
__global__ __launch_bounds__(256) void ydiag_kernel(const float* __restrict__ Dparam)
{
    int c = blockIdx.x, h = blockIdx.y, g = h >> 4;
    int tid = threadIdx.x, tx = tid & 15, ty = tid >> 4;
    __shared__ float xs[CSZ][DP];
    __shared__ float acsS[CSZ];
    __shared__ float dts[CSZ];

    for (int i = tid; i < CSZ * DP / 4; i += 256) {
        int r = i >> 4, q = i & 15;
        *(float4*)&xs[r][q * 4] =
            *(const float4*)(g_xbc + (size_t)(c * CSZ + r) * DCONV + h * DP + q * 4);
    }
    if (tid < CSZ) {
        dts[tid]  = g_dt[(c * CSZ + tid) * NH + h];
        acsS[tid] = g_acs[(c * NH + h) * CSZ + tid];
    }
    __syncthreads();

    float acs_l[8];
#pragma unroll
    for (int i = 0; i < 8; i++) acs_l[i] = acsS[ty * 8 + i];

    float acc[8][4];
#pragma unroll
    for (int i = 0; i < 8; i++)
#pragma unroll
        for (int j = 0; j < 4; j++) acc[i][j] = 0.f;

    const float* cbBase = g_cbt + (size_t)(c * NG + g) * CSZ * CSZ;
    const int lmax = ty * 8 + 7;
    for (int s = 0; s <= lmax; s++) {
        float av  = acsS[s];
        float dsv = dts[s];
        float4 cb0 = *(const float4*)(cbBase + (size_t)s * CSZ + ty * 8);
        float4 cb1 = *(const float4*)(cbBase + (size_t)s * CSZ + ty * 8 + 4);
        float cb[8] = {cb0.x, cb0.y, cb0.z, cb0.w, cb1.x, cb1.y, cb1.z, cb1.w};
        float4 xv4 = *(const float4*)&xs[s][tx * 4];
        float xv[4] = {xv4.x, xv4.y, xv4.z, xv4.w};
#pragma unroll
        for (int i = 0; i < 8; i++) {
            int l = ty * 8 + i;
            float f = 0.f;
            if (s <= l) f = cb[i] * __expf(fminf(acs_l[i] - av, 0.f)) * dsv;
#pragma unroll
            for (int j = 0; j < 4; j++) acc[i][j] += f * xv[j];
        }
    }
    const float dcoef = Dparam[h];
#pragma unroll
    for (int i = 0; i < 8; i++) {
        int l = ty * 8 + i;
        float4 xr = *(const float4*)&xs[l][tx * 4];
        float4 o = make_float4(acc[i][0] + dcoef * xr.x, acc[i][1] + dcoef * xr.y,
                               acc[i][2] + dcoef * xr.z, acc[i][3] + dcoef * xr.w);
        *(float4*)(g_y + (size_t)(c * CSZ + l) * DINTER + h * DP + tx * 4) = o;
    }
}

// ---------------- Local chunk states ----------------
__global__ __launch_bounds__(256) void states_kernel()
{
    int c = blockIdx.x, h = blockIdx.y, g = h >> 4;
    int tid = threadIdx.x, tx = tid & 15, ty = tid >> 4;
    __shared__ float Bsh[32][DN];
    __shared__ float xds[32][DP];
    __shared__ float dec[32];
    float acc[4][8];
#pragma unroll
    for (int i = 0; i < 4; i++)
#pragma unroll
        for (int j = 0; j < 8; j++) acc[i][j] = 0.f;

    const float al = g_alast[c * NH + h];
    for (int l0 = 0; l0 < CSZ; l0 += 32) {
        for (int i = tid; i < 32 * DN / 4; i += 256) {
            int r = i >> 5, q = i & 31;
            *(float4*)&Bsh[r][q * 4] = *(const float4*)(
                g_xbc + (size_t)(c * CSZ + l0 + r) * DCONV + DINTER + g * DN + q * 4);
        }
        for (int i = tid; i < 32 * DP / 4; i += 256) {
            int r = i >> 4, q = i & 15;
            int t = c * CSZ + l0 + r;
            float4 xv = *(const float4*)(g_xbc + (size_t)t * DCONV + h * DP + q * 4);
            float d = g_dt[t * NH + h];
            xv.x *= d; xv.y *= d; xv.z *= d; xv.w *= d;
            *(float4*)&xds[r][q * 4] = xv;
        }
        if (tid < 32) dec[tid] = __expf(al - g_acs[(c * NH + h) * CSZ + l0 + tid]);
        __syncthreads();
#pragma unroll 8
        for (int ll = 0; ll < 32; ll++) {
            float d = dec[ll];
            float4 b0 = *(const float4*)&Bsh[ll][tx * 8];
            float4 b1 = *(const float4*)&Bsh[ll][tx * 8 + 4];
            float bb[8] = {b0.x, b0.y, b0.z, b0.w, b1.x, b1.y, b1.z, b1.w};
            float4 xv = *(const float4*)&xds[ll][ty * 4];
            float xp[4] = {xv.x * d, xv.y * d, xv.z * d, xv.w * d};
#pragma unroll
            for (int pi = 0; pi < 4; pi++)
#pragma unroll
                for (int nj = 0; nj < 8; nj++) acc[pi][nj] += xp[pi] * bb[nj];
        }
        __syncthreads();
    }
    float* out = g_states + (size_t)(c * NH + h) * DP * DN;
#pragma unroll
    for (int pi = 0; pi < 4; pi++) {
        int p = ty * 4 + pi;
        *(float4*)(out + (size_t)p * DN + tx * 8)     = make_float4(acc[pi][0], acc[pi][1], acc[pi][2], acc[pi][3]);
        *(float4*)(out + (size_t)p * DN + tx * 8 + 4) = make_float4(acc[pi][4], acc[pi][5], acc[pi][6], acc[pi][7]);
    }
}

// ---------------- Inter-chunk scan ----------------
__global__ void prefix_kernel()
{
    int idx = blockIdx.x * blockDim.x + threadIdx.x;
    if (idx >= NH * DP * DN) return;
    int h = idx >> 13;
    float s = 0.f;
#pragma unroll
    for (int c = 0; c < NCH; c++) {
        size_t off = (size_t)c * NH * DP * DN + idx;
        g_prefix[off] = s;
        s = __expf(g_alast[c * NH + h]) * s + g_states[off];
    }
}

// ---------------- Y_off ----------------
__global__ __launch_bounds__(256) void yoff_kernel()
{
    int c = blockIdx.x, h = blockIdx.y, g = h >> 4;
    int tid = threadIdx.x, tx = tid & 15, ty = tid >> 4;
    __shared__ float Cs[CSZ][32];
    __shared__ float Pf[DP][33];
    __shared__ float acsS[CSZ];
    if (tid < CSZ) acsS[tid] = g_acs[(c * NH + h) * CSZ + tid];

    float acc[8][4];
#pragma unroll
    for (int i = 0; i < 8; i++)
#pragma unroll
        for (int j = 0; j < 4; j++) acc[i][j] = 0.f;

    for (int n0 = 0; n0 < DN; n0 += 32) {
        for (int i = tid; i < CSZ * 8; i += 256) {
            int r = i >> 3, q = i & 7;
            *(float4*)&Cs[r][q * 4] = *(const float4*)(
                g_xbc + (size_t)(c * CSZ + r) * DCONV + DINTER + NG * DN + g * DN + n0 + q * 4);
        }
        for (int i = tid; i < DP * 8; i += 256) {
            int r = i >> 3, q = i & 7;
            float4 v = *(const float4*)(
                g_prefix + ((size_t)(c * NH + h) * DP + r) * DN + n0 + q * 4);
            Pf[r][q * 4 + 0] = v.x; Pf[r][q * 4 + 1] = v.y;
            Pf[r][q * 4 + 2] = v.z; Pf[r][q * 4 + 3] = v.w;
        }
        __syncthreads();
#pragma unroll 8
        for (int nn = 0; nn < 32; nn++) {
            float cl[8], pv[4];
#pragma unroll
            for (int i = 0; i < 8; i++) cl[i] = Cs[ty * 8 + i][nn];
#pragma unroll
            for (int j = 0; j < 4; j++) pv[j] = Pf[tx * 4 + j][nn];
#pragma unroll
            for (int i = 0; i < 8; i++)
#pragma unroll
                for (int j = 0; j < 4; j++) acc[i][j] += cl[i] * pv[j];
        }
        __syncthreads();
    }
#pragma unroll
    for (int i = 0; i < 8; i++) {
        int l = ty * 8 + i;
        float e = __expf(acsS[l]);
        float* yp = g_y + (size_t)(c * CSZ + l) * DINTER + h * DP + tx * 4;
        float4 y = *(float4*)yp;
        y.x += e * acc[i][0]; y.y += e * acc[i][1];
        y.z += e * acc[i][2]; y.w += e * acc[i][3];
        *(float4*)yp = y;
    }
}

// ---------------- RMSNorm * norm_w * silu(gate) ----------------
__global__ __launch_bounds__(256) void rms_gate_kernel(const float* __restrict__ norm_w)
{
    int t = blockIdx.x, tid = threadIdx.x;
    const size_t base = (size_t)t * DINTER;
    float ss = 0.f;
    for (int i = tid; i < DINTER; i += 256) {
        float v = g_y[base + i];
        ss += v * v;
    }
    __shared__ float red[256];
    red[tid] = ss;
    __syncthreads();
#pragma unroll
    for (int o = 128; o > 0; o >>= 1) {
        if (tid < o) red[tid] += red[tid + o];
        __syncthreads();
    }
    float inv = rsqrtf(red[0] / (float)DINTER + RMS_EPS);
    for (int i = tid; i < DINTER; i += 256) {
        float v = g_y[base + i] * inv * norm_w[i];
        float gt = g_proj[(size_t)t * DPROJ + i];
        v *= gt / (1.f + __expf(-gt));
        g_y[base + i] = v;
    }
}

// ---------------- Launch ----------------
extern "C" void kernel_launch(void* const* d_in, const int* in_sizes, int n_in,
                              void* d_out, int out_size)
{
    (void)in_sizes; (void)n_in; (void)out_size;
    const float* hs         = (const float*)d_in[0];
    const float* in_proj_w  = (const float*)d_in[1];
    const float* conv_w     = (const float*)d_in[2];
    const float* conv_b     = (const float*)d_in[3];
    const float* dt_bias    = (const float*)d_in[4];
    const float* A_log      = (const float*)d_in[5];
    const float* Dp         = (const float*)d_in[6];
    const float* norm_w     = (const float*)d_in[7];
    const float* out_proj_w = (const float*)d_in[8];
    float* out = (float*)d_out;

    void *p_proj = nullptr, *p_y = nullptr;
    cudaGetSymbolAddress(&p_proj, g_proj);
    cudaGetSymbolAddress(&p_y, g_y);

    // 1) in-proj GEMM (tf32 tensor cores): (2048 x 18560) = hs @ W^T
    gemm_tf32_kernel<<<dim3(DPROJ / 128, LSEQ / 128), 256>>>(hs, in_proj_w, (float*)p_proj, DPROJ, DMODEL);
    // 2) causal depthwise conv + silu
    conv_silu_kernel<<<(LSEQ * DCONV + 255) / 256, 256>>>(conv_w, conv_b);
    // 3) dt softplus + per-chunk cumsum of A*dt
    dt_scan_kernel<<<dim3(NCH, NH), CSZ>>>(dt_bias, A_log);
    // 4) C·B^T per (chunk, group)
    cb_kernel<<<dim3(NCH, NG), 256>>>();
    // 5) intra-chunk (diagonal) output + D residual
    ydiag_kernel<<<dim3(NCH, NH), 256>>>(Dp);
    // 6) local chunk states
    states_kernel<<<dim3(NCH, NH), 256>>>();
    // 7) inter-chunk state scan
    prefix_kernel<<<(NH * DP * DN + 255) / 256, 256>>>();
    // 8) off-diagonal output (adds into g_y)
    yoff_kernel<<<dim3(NCH, NH), 256>>>();
    // 9) gated RMSNorm (in place)
    rms_gate_kernel<<<LSEQ, 256>>>(norm_w);
    // 10) out-proj GEMM (tf32): (2048 x 4096) = y @ W^T
    gemm_tf32_kernel<<<dim3(DMODEL / 128, LSEQ / 128), 256>>>((const float*)p_y, out_proj_w, out, DMODEL, DINTER);
}

// round 4
// speedup vs baseline: 2.5856x; 1.0532x over previous
#include <cuda_runtime.h>
#include <math.h>
#include <stdint.h>

// ---------------- Problem constants ----------------
#define LSEQ   2048
#define DMODEL 4096
#define NH     128
#define DP     64
#define NG     8
#define DN     128
#define CSZ    128
#define NCH    (LSEQ / CSZ)
#define KCONV  4
#define DINTER 8192
#define DCONV  10240
#define DPROJ  18560
#define RMS_EPS 1e-5f

// ---------------- Scratch ----------------
__device__ float g_proj[LSEQ * DPROJ];
__device__ float g_xbc[LSEQ * DCONV];
__device__ float g_dt[LSEQ * NH];
__device__ float g_acs[NCH * NH * CSZ];
__device__ float g_alast[NCH * NH];
__device__ float g_cbt[NCH * NG * CSZ * CSZ];
__device__ float g_states[NCH * NH * DP * DN];
__device__ float g_prefix[NCH * NH * DP * DN];
__device__ float g_y[LSEQ * DINTER];

// ---------------- helpers ----------------
__device__ __forceinline__ uint32_t f2tf32(float f) {
    uint32_t r;
    asm("cvt.rna.tf32.f32 %0, %1;" : "=r"(r) : "f"(f));
    return r;
}
__device__ __forceinline__ void mma_tf32(float c[4], const uint32_t a[4], const uint32_t b[2]) {
    asm volatile(
        "mma.sync.aligned.m16n8k8.row.col.f32.tf32.tf32.f32 "
        "{%0,%1,%2,%3}, {%4,%5,%6,%7}, {%8,%9}, {%0,%1,%2,%3};"
        : "+f"(c[0]), "+f"(c[1]), "+f"(c[2]), "+f"(c[3])
        : "r"(a[0]), "r"(a[1]), "r"(a[2]), "r"(a[3]), "r"(b[0]), "r"(b[1]));
}
// silu via single-MUFU tanh.approx: silu(x) = 0.5*x*(1+tanh(x/2))
__device__ __forceinline__ float fast_silu(float x) {
    float t;
    asm("tanh.approx.f32 %0, %1;" : "=f"(t) : "f"(x * 0.5f));
    return 0.5f * x * (1.f + t);
}

// ---------------- tf32 GEMM: C[M,Nd] = A[M,Kd] * B[Nd,Kd]^T (row-major) ----------------
// BM=128, BN=128, BK=16, 256 threads (8 warps), warp tile 64x32, double-buffered smem.
__global__ __launch_bounds__(256) void gemm_tf32_kernel(
    const float* __restrict__ A, const float* __restrict__ B, float* __restrict__ C,
    int Nd, int Kd)
{
    __shared__ uint32_t As[2][128][20];
    __shared__ uint32_t Bs[2][128][20];

    const int tid  = threadIdx.x;
    const int lane = tid & 31, warp = tid >> 5;
    const int wm = (warp >> 2) * 64;
    const int wn = (warp & 3) * 32;
    const int g  = lane >> 2, tq = lane & 3;
    const int bm = blockIdx.y * 128, bn = blockIdx.x * 128;

    const int r0 = tid >> 2, c4 = (tid & 3) * 4;
    const int r1 = r0 + 64;
    const float* Ag0 = A + (size_t)(bm + r0) * Kd + c4;
    const float* Ag1 = A + (size_t)(bm + r1) * Kd + c4;
    const float* Bg0 = B + (size_t)(bn + r0) * Kd + c4;
    const float* Bg1 = B + (size_t)(bn + r1) * Kd + c4;

    float acc[4][4][4];
#pragma unroll
    for (int mt = 0; mt < 4; mt++)
#pragma unroll
        for (int nt = 0; nt < 4; nt++)
#pragma unroll
            for (int q = 0; q < 4; q++) acc[mt][nt][q] = 0.f;

    {
        float4 a0 = *(const float4*)(Ag0);
        float4 a1 = *(const float4*)(Ag1);
        float4 b0 = *(const float4*)(Bg0);
        float4 b1 = *(const float4*)(Bg1);
        As[0][r0][c4+0]=f2tf32(a0.x); As[0][r0][c4+1]=f2tf32(a0.y); As[0][r0][c4+2]=f2tf32(a0.z); As[0][r0][c4+3]=f2tf32(a0.w);
        As[0][r1][c4+0]=f2tf32(a1.x); As[0][r1][c4+1]=f2tf32(a1.y); As[0][r1][c4+2]=f2tf32(a1.z); As[0][r1][c4+3]=f2tf32(a1.w);
        Bs[0][r0][c4+0]=f2tf32(b0.x); Bs[0][r0][c4+1]=f2tf32(b0.y); Bs[0][r0][c4+2]=f2tf32(b0.z); Bs[0][r0][c4+3]=f2tf32(b0.w);
        Bs[0][r1][c4+0]=f2tf32(b1.x); Bs[0][r1][c4+1]=f2tf32(b1.y); Bs[0][r1][c4+2]=f2tf32(b1.z); Bs[0][r1][c4+3]=f2tf32(b1.w);
    }
    __syncthreads();

    const int KT = Kd >> 4;
    int cur = 0;
    for (int kt = 0; kt < KT; kt++) {
        float4 na0, na1, nb0, nb1;
        const bool has_next = (kt + 1 < KT);
        if (has_next) {
            int ko = (kt + 1) << 4;
            na0 = *(const float4*)(Ag0 + ko);
            na1 = *(const float4*)(Ag1 + ko);
            nb0 = *(const float4*)(Bg0 + ko);
            nb1 = *(const float4*)(Bg1 + ko);
        }

#pragma unroll
        for (int ks = 0; ks < 2; ks++) {
            const int ko = ks * 8;
            uint32_t af[4][4], bf[4][2];
#pragma unroll
            for (int mt = 0; mt < 4; mt++) {
                const int m0 = wm + mt * 16;
                af[mt][0] = As[cur][m0 + g    ][ko + tq];
                af[mt][1] = As[cur][m0 + g + 8][ko + tq];
                af[mt][2] = As[cur][m0 + g    ][ko + tq + 4];
                af[mt][3] = As[cur][m0 + g + 8][ko + tq + 4];
            }
#pragma unroll
            for (int nt = 0; nt < 4; nt++) {
                const int n0 = wn + nt * 8;
                bf[nt][0] = Bs[cur][n0 + g][ko + tq];
                bf[nt][1] = Bs[cur][n0 + g][ko + tq + 4];
            }
#pragma unroll
            for (int mt = 0; mt < 4; mt++)
#pragma unroll
                for (int nt = 0; nt < 4; nt++)
                    mma_tf32(acc[mt][nt], af[mt], bf[nt]);
        }

        if (has_next) {
            int nxt = cur ^ 1;
            As[nxt][r0][c4+0]=f2tf32(na0.x); As[nxt][r0][c4+1]=f2tf32(na0.y); As[nxt][r0][c4+2]=f2tf32(na0.z); As[nxt][r0][c4+3]=f2tf32(na0.w);
            As[nxt][r1][c4+0]=f2tf32(na1.x); As[nxt][r1][c4+1]=f2tf32(na1.y); As[nxt][r1][c4+2]=f2tf32(na1.z); As[nxt][r1][c4+3]=f2tf32(na1.w);
            Bs[nxt][r0][c4+0]=f2tf32(nb0.x); Bs[nxt][r0][c4+1]=f2tf32(nb0.y); Bs[nxt][r0][c4+2]=f2tf32(nb0.z); Bs[nxt][r0][c4+3]=f2tf32(nb0.w);
            Bs[nxt][r1][c4+0]=f2tf32(nb1.x); Bs[nxt][r1][c4+1]=f2tf32(nb1.y); Bs[nxt][r1][c4+2]=f2tf32(nb1.z); Bs[nxt][r1][c4+3]=f2tf32(nb1.w);
            cur = nxt;
        }
        __syncthreads();
    }

#pragma unroll
    for (int mt = 0; mt < 4; mt++) {
#pragma unroll
        for (int nt = 0; nt < 4; nt++) {
            const int row = bm + wm + mt * 16 + g;
            const int col = bn + wn + nt * 8 + 2 * tq;
            *(float2*)&C[(size_t)row * Nd + col]       = make_float2(acc[mt][nt][0], acc[mt][nt][1]);
            *(float2*)&C[(size_t)(row + 8) * Nd + col] = make_float2(acc[mt][nt][2], acc[mt][nt][3]);
        }
    }
}

// ---------------- Depthwise causal conv (K=4) + SiLU ----------------
__global__ void conv_silu_kernel(const float* __restrict__ conv_w, const float* __restrict__ conv_b)
{
    int idx = blockIdx.x * blockDim.x + threadIdx.x;
    if (idx >= LSEQ * DCONV) return;
    int t = idx / DCONV, c = idx % DCONV;
    float acc = conv_b[c];
    const float* w = conv_w + c * KCONV;
#pragma unroll
    for (int k = 0; k < KCONV; k++) {
        int tt = t + k - (KCONV - 1);
        if (tt >= 0) acc += w[k] * g_proj[(size_t)tt * DPROJ + DINTER + c];
    }
    g_xbc[idx] = fast_silu(acc);
}

// ---------------- dt softplus + per-chunk cumsum of A*dt ----------------
__global__ __launch_bounds__(CSZ) void dt_scan_kernel(
    const float* __restrict__ dt_bias, const float* __restrict__ A_log)
{
    int c = blockIdx.x, h = blockIdx.y, l = threadIdx.x;
    int t = c * CSZ + l;
    float raw = g_proj[(size_t)t * DPROJ + DINTER + DCONV + h] + dt_bias[h];
    float dtp = (raw > 0.f) ? (raw + log1pf(__expf(-raw))) : log1pf(__expf(raw));
    g_dt[t * NH + h] = dtp;
    float a = -__expf(A_log[h]) * dtp;

    __shared__ float s[CSZ];
    s[l] = a;
    __syncthreads();
#pragma unroll
    for (int off = 1; off < CSZ; off <<= 1) {
        float v = (l >= off) ? s[l - off] : 0.f;
        __syncthreads();
        s[l] += v;
        __syncthreads();
    }
    g_acs[(c * NH + h) * CSZ + l] = s[l];
    if (l == CSZ - 1) g_alast[c * NH + h] = s[l];
}

// ---------------- CBt[c][g][s][l] = sum_n C[l,n]*B[s,n] ----------------
__global__ __launch_bounds__(256) void cb_kernel()
{
    int c = blockIdx.x, g = blockIdx.y;
    int tid = threadIdx.x, tx = tid & 15, ty = tid >> 4;
    __shared__ float Csn[16][CSZ];
    __shared__ float Bsn[16][CSZ];
    float acc[8][8];
#pragma unroll
    for (int i = 0; i < 8; i++)
#pragma unroll
        for (int j = 0; j < 8; j++) acc[i][j] = 0.f;

    const float* Cg = g_xbc + DINTER + NG * DN + g * DN;
    const float* Bg = g_xbc + DINTER + g * DN;

    for (int n0 = 0; n0 < DN; n0 += 16) {
        for (int i = tid; i < CSZ * 4; i += 256) {
            int r = i >> 2, q = i & 3;
            const size_t row = (size_t)(c * CSZ + r) * DCONV + n0 + q * 4;
            float4 cv = *(const float4*)(Cg + row);
            float4 bv = *(const float4*)(Bg + row);
            Csn[q * 4 + 0][r] = cv.x; Csn[q * 4 + 1][r] = cv.y;
            Csn[q * 4 + 2][r] = cv.z; Csn[q * 4 + 3][r] = cv.w;
            Bsn[q * 4 + 0][r] = bv.x; Bsn[q * 4 + 1][r] = bv.y;
            Bsn[q * 4 + 2][r] = bv.z; Bsn[q * 4 + 3][r] = bv.w;
        }
        __syncthreads();
#pragma unroll
        for (int nn = 0; nn < 16; nn++) {
            float4 c0 = *(const float4*)&Csn[nn][tx * 8];
            float4 c1 = *(const float4*)&Csn[nn][tx * 8 + 4];
            float4 b0 = *(const float4*)&Bsn[nn][ty * 8];
            float4 b1 = *(const float4*)&Bsn[nn][ty * 8 + 4];
            float cl[8] = {c0.x, c0.y, c0.z, c0.w, c1.x, c1.y, c1.z, c1.w};
            float bs[8] = {b0.x, b0.y, b0.z, b0.w, b1.x, b1.y, b1.z, b1.w};
#pragma unroll
            for (int si = 0; si < 8; si++)
#pragma unroll
                for (int li = 0; li < 8; li++) acc[si][li] += cl[li] * bs[si];
        }
        __syncthreads();
    }
    float* out = g_cbt + (size_t)(c * NG + g) * CSZ * CSZ;
#pragma unroll
    for (int si = 0; si < 8; si++) {
        int s = ty * 8 + si;
        *(float4*)(out + (size_t)s * CSZ + tx * 8)     = make_float4(acc[si][0], acc[si][1], acc[si][2], acc[si][3]);
        *(float4*)(out + (size_t)s * CSZ + tx * 8 + 4) = make_float4(acc[si][4], acc[si][5], acc[si][6], acc[si][7]);
    }
}

// ---------------- Y_diag + D residual (decay matrix precomputed in smem tiles) ----------------
// M[l][s] = CB[s,l] * exp(acs_l - acs_s) * dt_s  computed ONCE per (l,s) per CTA.
__global__ __launch_bounds__(256) void ydiag_kernel(const float* __restrict__ Dparam)
{
    int c = blockIdx.x, h = blockIdx.y, g = h >> 4;
    int tid = threadIdx.x, tx = tid & 15, ty = tid >> 4; // l = ty*8+i, p = tx*4+j
    __shared__ float xs[CSZ][DP];      // 32KB
    __shared__ float Ms[CSZ][17];      // factor tile: Ms[l][ss], 8.5KB
    __shared__ float acsS[CSZ];
    __shared__ float dts[CSZ];

    for (int i = tid; i < CSZ * DP / 4; i += 256) {
        int r = i >> 4, q = i & 15;
        *(float4*)&xs[r][q * 4] =
            *(const float4*)(g_xbc + (size_t)(c * CSZ + r) * DCONV + h * DP + q * 4);
    }
    if (tid < CSZ) {
        dts[tid]  = g_dt[(c * CSZ + tid) * NH + h];
        acsS[tid] = g_acs[(c * NH + h) * CSZ + tid];
    }
    __syncthreads();

    float acc[8][4];
#pragma unroll
    for (int i = 0; i < 8; i++)
#pragma unroll
        for (int j = 0; j < 4; j++) acc[i][j] = 0.f;

    const float* cbBase = g_cbt + (size_t)(c * NG + g) * CSZ * CSZ;
    const int ss_row = tid >> 4;   // 0..15 (s within tile)
    const int lg     = tid & 15;   // l-group: l = lg*8+k

    for (int s0 = 0; s0 < CSZ; s0 += 16) {
        // cooperative precompute of the 128x16 factor tile (1 exp per live entry)
        {
            const int s = s0 + ss_row;
            const float as  = acsS[s];
            const float dsv = dts[s];
            const float* cbRow = cbBase + (size_t)s * CSZ;
#pragma unroll
            for (int k = 0; k < 8; k++) {
                const int l = lg * 8 + k;
                float f = 0.f;
                if (s <= l) f = cbRow[l] * __expf(acsS[l] - as) * dsv;
                Ms[l][ss_row] = f;
            }
        }
        __syncthreads();

#pragma unroll
        for (int ss = 0; ss < 16; ss++) {
            const int s = s0 + ss;
            float msv[8];
#pragma unroll
            for (int i = 0; i < 8; i++) msv[i] = Ms[ty * 8 + i][ss];
            float4 xv4 = *(const float4*)&xs[s][tx * 4];
#pragma unroll
            for (int i = 0; i < 8; i++) {
                acc[i][0] += msv[i] * xv4.x;
                acc[i][1] += msv[i] * xv4.y;
                acc[i][2] += msv[i] * xv4.z;
                acc[i][3] += msv[i] * xv4.w;
            }
        }
        __syncthreads();
    }

    const float dcoef = Dparam[h];
#pragma unroll
    for (int i = 0; i < 8; i++) {
        int l = ty * 8 + i;
        float4 xr = *(const float4*)&xs[l][tx * 4];
        float4 o = make_float4(acc[i][0] + dcoef * xr.x, acc[i][1] + dcoef * xr.y,
                               acc[i][2] + dcoef * xr.z, acc[i][3] + dcoef * xr.w);
        *(float4*)(g_y + (size_t)(c * CSZ + l) * DINTER + h * DP + tx * 4) = o;
    }
}

// ---------------- Local chunk states ----------------
__global__ __launch_bounds__(256) void states_kernel()
{
    int c = blockIdx.x, h = blockIdx.y, g = h >> 4;
    int tid = threadIdx.x, tx = tid & 15, ty = tid >> 4;
    __shared__ float Bsh[32][DN];
    __shared__ float xds[32][DP];
    __shared__ float dec[32];
    float acc[4][8];
#pragma unroll
    for (int i = 0; i < 4; i++)
#pragma unroll
        for (int j = 0; j < 8; j++) acc[i][j] = 0.f;

    const float al = g_alast[c * NH + h];
    for (int l0 = 0; l0 < CSZ; l0 += 32) {
        for (int i = tid; i < 32 * DN / 4; i += 256) {
            int r = i >> 5, q = i & 31;
            *(float4*)&Bsh[r][q * 4] = *(const float4*)(
                g_xbc + (size_t)(c * CSZ + l0 + r) * DCONV + DINTER + g * DN + q * 4);
        }
        for (int i = tid; i < 32 * DP / 4; i += 256) {
            int r = i >> 4, q = i & 15;
            int t = c * CSZ + l0 + r;
            float4 xv = *(const float4*)(g_xbc + (size_t)t * DCONV + h * DP + q * 4);
            float d = g_dt[t * NH + h];
            xv.x *= d; xv.y *= d; xv.z *= d; xv.w *= d;
            *(float4*)&xds[r][q * 4] = xv;
        }
        if (tid < 32) dec[tid] = __expf(al - g_acs[(c * NH + h) * CSZ + l0 + tid]);
        __syncthreads();
#pragma unroll 8
        for (int ll = 0; ll < 32; ll++) {
            float d = dec[ll];
            float4 b0 = *(const float4*)&Bsh[ll][tx * 8];
            float4 b1 = *(const float4*)&Bsh[ll][tx * 8 + 4];
            float bb[8] = {b0.x, b0.y, b0.z, b0.w, b1.x, b1.y, b1.z, b1.w};
            float4 xv = *(const float4*)&xds[ll][ty * 4];
            float xp[4] = {xv.x * d, xv.y * d, xv.z * d, xv.w * d};
#pragma unroll
            for (int pi = 0; pi < 4; pi++)
#pragma unroll
                for (int nj = 0; nj < 8; nj++) acc[pi][nj] += xp[pi] * bb[nj];
        }
        __syncthreads();
    }
    float* out = g_states + (size_t)(c * NH + h) * DP * DN;
#pragma unroll
    for (int pi = 0; pi < 4; pi++) {
        int p = ty * 4 + pi;
        *(float4*)(out + (size_t)p * DN + tx * 8)     = make_float4(acc[pi][0], acc[pi][1], acc[pi][2], acc[pi][3]);
        *(float4*)(out + (size_t)p * DN + tx * 8 + 4) = make_float4(acc[pi][4], acc[pi][5], acc[pi][6], acc[pi][7]);
    }
}

// ---------------- Inter-chunk scan ----------------
__global__ void prefix_kernel()
{
    int idx = blockIdx.x * blockDim.x + threadIdx.x;
    if (idx >= NH * DP * DN) return;
    int h = idx >> 13;
    float s = 0.f;
#pragma unroll
    for (int c = 0; c < NCH; c++) {
        size_t off = (size_t)c * NH * DP * DN + idx;
        g_prefix[off] = s;
        s = __expf(g_alast[c * NH + h]) * s + g_states[off];
    }
}

// ---------------- Y_off ----------------
__global__ __launch_bounds__(256) void yoff_kernel()
{
    int c = blockIdx.x, h = blockIdx.y, g = h >> 4;
    int tid = threadIdx.x, tx = tid & 15, ty = tid >> 4;
    __shared__ float Cs[CSZ][32];
    __shared__ float Pf[DP][33];
    __shared__ float acsS[CSZ];
    if (tid < CSZ) acsS[tid] = g_acs[(c * NH + h) * CSZ + tid];

    float acc[8][4];
#pragma unroll
    for (int i = 0; i < 8; i++)
#pragma unroll
        for (int j = 0; j < 4; j++) acc[i][j] = 0.f;

    for (int n0 = 0; n0 < DN; n0 += 32) {
        for (int i = tid; i < CSZ * 8; i += 256) {
            int r = i >> 3, q = i & 7;
            *(float4*)&Cs[r][q * 4] = *(const float4*)(
                g_xbc + (size_t)(c * CSZ + r) * DCONV + DINTER + NG * DN + g * DN + n0 + q * 4);
        }
        for (int i = tid; i < DP * 8; i += 256) {
            int r = i >> 3, q = i & 7;
            float4 v = *(const float4*)(
                g_prefix + ((size_t)(c * NH + h) * DP + r) * DN + n0 + q * 4);
            Pf[r][q * 4 + 0] = v.x; Pf[r][q * 4 + 1] = v.y;
            Pf[r][q * 4 + 2] = v.z; Pf[r][q * 4 + 3] = v.w;
        }
        __syncthreads();
#pragma unroll 8
        for (int nn = 0; nn < 32; nn++) {
            float cl[8], pv[4];
#pragma unroll
            for (int i = 0; i < 8; i++) cl[i] = Cs[ty * 8 + i][nn];
#pragma unroll
            for (int j = 0; j < 4; j++) pv[j] = Pf[tx * 4 + j][nn];
#pragma unroll
            for (int i = 0; i < 8; i++)
#pragma unroll
                for (int j = 0; j < 4; j++) acc[i][j] += cl[i] * pv[j];
        }
        __syncthreads();
    }
#pragma unroll
    for (int i = 0; i < 8; i++) {
        int l = ty * 8 + i;
        float e = __expf(acsS[l]);
        float* yp = g_y + (size_t)(c * CSZ + l) * DINTER + h * DP + tx * 4;
        float4 y = *(float4*)yp;
        y.x += e * acc[i][0]; y.y += e * acc[i][1];
        y.z += e * acc[i][2]; y.w += e * acc[i][3];
        *(float4*)yp = y;
    }
}

// ---------------- RMSNorm * norm_w * silu(gate) ----------------
__global__ __launch_bounds__(256) void rms_gate_kernel(const float* __restrict__ norm_w)
{
    int t = blockIdx.x, tid = threadIdx.x;
    const size_t base = (size_t)t * DINTER;
    float ss = 0.f;
    for (int i = tid; i < DINTER; i += 256) {
        float v = g_y[base + i];
        ss += v * v;
    }
    __shared__ float red[256];
    red[tid] = ss;
    __syncthreads();
#pragma unroll
    for (int o = 128; o > 0; o >>= 1) {
        if (tid < o) red[tid] += red[tid + o];
        __syncthreads();
    }
    float inv = rsqrtf(red[0] / (float)DINTER + RMS_EPS);
    for (int i = tid; i < DINTER; i += 256) {
        float v = g_y[base + i] * inv * norm_w[i];
        v *= fast_silu(g_proj[(size_t)t * DPROJ + i]);
        g_y[base + i] = v;
    }
}

// ---------------- Launch ----------------
extern "C" void kernel_launch(void* const* d_in, const int* in_sizes, int n_in,
                              void* d_out, int out_size)
{
    (void)in_sizes; (void)n_in; (void)out_size;
    const float* hs         = (const float*)d_in[0];
    const float* in_proj_w  = (const float*)d_in[1];
    const float* conv_w     = (const float*)d_in[2];
    const float* conv_b     = (const float*)d_in[3];
    const float* dt_bias    = (const float*)d_in[4];
    const float* A_log      = (const float*)d_in[5];
    const float* Dp         = (const float*)d_in[6];
    const float* norm_w     = (const float*)d_in[7];
    const float* out_proj_w = (const float*)d_in[8];
    float* out = (float*)d_out;

    void *p_proj = nullptr, *p_y = nullptr;
    cudaGetSymbolAddress(&p_proj, g_proj);
    cudaGetSymbolAddress(&p_y, g_y);

    // 1) in-proj GEMM (tf32 tensor cores): (2048 x 18560) = hs @ W^T
    gemm_tf32_kernel<<<dim3(DPROJ / 128, LSEQ / 128), 256>>>(hs, in_proj_w, (float*)p_proj, DPROJ, DMODEL);
    // 2) causal depthwise conv + silu
    conv_silu_kernel<<<(LSEQ * DCONV + 255) / 256, 256>>>(conv_w, conv_b);
    // 3) dt softplus + per-chunk cumsum of A*dt
    dt_scan_kernel<<<dim3(NCH, NH), CSZ>>>(dt_bias, A_log);
    // 4) C·B^T per (chunk, group)
    cb_kernel<<<dim3(NCH, NG), 256>>>();
    // 5) intra-chunk (diagonal) output + D residual
    ydiag_kernel<<<dim3(NCH, NH), 256>>>(Dp);
    // 6) local chunk states
    states_kernel<<<dim3(NCH, NH), 256>>>();
    // 7) inter-chunk state scan
    prefix_kernel<<<(NH * DP * DN + 255) / 256, 256>>>();
    // 8) off-diagonal output (adds into g_y)
    yoff_kernel<<<dim3(NCH, NH), 256>>>();
    // 9) gated RMSNorm (in place)
    rms_gate_kernel<<<LSEQ, 256>>>(norm_w);
    // 10) out-proj GEMM (tf32): (2048 x 4096) = y @ W^T
    gemm_tf32_kernel<<<dim3(DMODEL / 128, LSEQ / 128), 256>>>((const float*)p_y, out_proj_w, out, DMODEL, DINTER);
}

// round 5
// speedup vs baseline: 2.9564x; 1.1434x over previous
#include <cuda_runtime.h>
#include <math.h>
#include <stdint.h>

// ---------------- Problem constants ----------------
#define LSEQ   2048
#define DMODEL 4096
#define NH     128
#define DP     64
#define NG     8
#define DN     128
#define CSZ    128
#define NCH    (LSEQ / CSZ)
#define KCONV  4
#define DINTER 8192
#define DCONV  10240
#define DPROJ  18560
#define RMS_EPS 1e-5f

// ---------------- Scratch ----------------
__device__ float g_proj[LSEQ * DPROJ];
__device__ float g_xbc[LSEQ * DCONV];
__device__ float g_dt[LSEQ * NH];
__device__ float g_acs[NCH * NH * CSZ];
__device__ float g_alast[NCH * NH];
__device__ float g_cbt[NCH * NG * CSZ * CSZ];
__device__ float g_states[NCH * NH * DP * DN];
__device__ float g_prefix[NCH * NH * DP * DN];
__device__ float g_y[LSEQ * DINTER];

// ---------------- helpers ----------------
__device__ __forceinline__ uint32_t f2tf32(float f) {
    uint32_t r;
    asm("cvt.rna.tf32.f32 %0, %1;" : "=r"(r) : "f"(f));
    return r;
}
__device__ __forceinline__ void mma_tf32(float c[4], const uint32_t a[4], const uint32_t b[2]) {
    asm volatile(
        "mma.sync.aligned.m16n8k8.row.col.f32.tf32.tf32.f32 "
        "{%0,%1,%2,%3}, {%4,%5,%6,%7}, {%8,%9}, {%0,%1,%2,%3};"
        : "+f"(c[0]), "+f"(c[1]), "+f"(c[2]), "+f"(c[3])
        : "r"(a[0]), "r"(a[1]), "r"(a[2]), "r"(a[3]), "r"(b[0]), "r"(b[1]));
}
__device__ __forceinline__ float fast_silu(float x) {
    float t;
    asm("tanh.approx.f32 %0, %1;" : "=f"(t) : "f"(x * 0.5f));
    return 0.5f * x * (1.f + t);
}
__device__ __forceinline__ uint32_t smem_u32(const void* p) {
    uint32_t a;
    asm("{ .reg .u64 t; cvta.to.shared.u64 t, %1; cvt.u32.u64 %0, t; }" : "=r"(a) : "l"(p));
    return a;
}
__device__ __forceinline__ void cp_async16(uint32_t saddr, const void* gaddr) {
    asm volatile("cp.async.cg.shared.global [%0], [%1], 16;" :: "r"(saddr), "l"(gaddr));
}
#define CP_COMMIT() asm volatile("cp.async.commit_group;" ::: "memory")
#define CP_WAIT(n)  asm volatile("cp.async.wait_group %0;" :: "n"(n) : "memory")

// ---------------- tf32 GEMM, cp.async 3-stage: C[M,Nd] = A[M,Kd]*B[Nd,Kd]^T ----------------
// BM=BN=128, BK=16, 256 threads (8 warps), warp tile 64x32.
// Smem: raw fp32, row stride 20 words (pad 4) -> conflict-free fragment LDS.
#define GSTAGES 3
#define ROWW    20                       // words per row
#define TILEW   (128 * ROWW)             // words per (A or B) stage tile
#define GEMM_DSMEM (GSTAGES * 2 * TILEW * 4)   // 61440 bytes

__global__ __launch_bounds__(256, 2) void gemm_tf32_kernel(
    const float* __restrict__ A, const float* __restrict__ B, float* __restrict__ C,
    int Nd, int Kd)
{
    extern __shared__ float smf[];
    float* const Abuf = smf;                       // [GSTAGES][128][ROWW]
    float* const Bbuf = smf + GSTAGES * TILEW;     // [GSTAGES][128][ROWW]
    const uint32_t sbaseA = smem_u32(Abuf);
    const uint32_t sbaseB = smem_u32(Bbuf);

    const int tid  = threadIdx.x;
    const int lane = tid & 31, warp = tid >> 5;
    const int wm = (warp >> 2) * 64;
    const int wn = (warp & 3) * 32;
    const int g  = lane >> 2, tq = lane & 3;
    const int bm = blockIdx.y * 128, bn = blockIdx.x * 128;

    // copy geometry: row pair (r0, r0+64), chunk q (16B)
    const int r0 = tid >> 2, q = (tid & 3) * 4;
    const float* Ag0 = A + (size_t)(bm + r0) * Kd + q;
    const float* Ag1 = Ag0 + (size_t)64 * Kd;
    const float* Bg0 = B + (size_t)(bn + r0) * Kd + q;
    const float* Bg1 = Bg0 + (size_t)64 * Kd;
    const uint32_t swA0 = sbaseA + (uint32_t)(r0 * ROWW + q) * 4;
    const uint32_t swA1 = swA0 + 64 * ROWW * 4;
    const uint32_t swB0 = sbaseB + (uint32_t)(r0 * ROWW + q) * 4;
    const uint32_t swB1 = swB0 + 64 * ROWW * 4;

    const int KT = Kd >> 4;

    // prefetch stages 0..GSTAGES-2
#pragma unroll
    for (int s = 0; s < GSTAGES - 1; s++) {
        const uint32_t so = (uint32_t)(s * TILEW * 4);
        const size_t ko = (size_t)s * 16;
        cp_async16(swA0 + so, Ag0 + ko);
        cp_async16(swA1 + so, Ag1 + ko);
        cp_async16(swB0 + so, Bg0 + ko);
        cp_async16(swB1 + so, Bg1 + ko);
        CP_COMMIT();
    }

    float acc[4][4][4];
#pragma unroll
    for (int mt = 0; mt < 4; mt++)
#pragma unroll
        for (int nt = 0; nt < 4; nt++)
#pragma unroll
            for (int qq = 0; qq < 4; qq++) acc[mt][nt][qq] = 0.f;

    int buf = 0;
    for (int kt = 0; kt < KT; kt++) {
        CP_WAIT(GSTAGES - 2);
        __syncthreads();

        // issue prefetch for stage kt+GSTAGES-1 into the buffer just freed
        const int pf = kt + GSTAGES - 1;
        if (pf < KT) {
            const int pb = pf % GSTAGES;
            const uint32_t so = (uint32_t)(pb * TILEW * 4);
            const size_t ko = (size_t)pf * 16;
            cp_async16(swA0 + so, Ag0 + ko);
            cp_async16(swA1 + so, Ag1 + ko);
            cp_async16(swB0 + so, Bg0 + ko);
            cp_async16(swB1 + so, Bg1 + ko);
        }
        CP_COMMIT();

        const float* As = Abuf + buf * TILEW;
        const float* Bs = Bbuf + buf * TILEW;
#pragma unroll
        for (int ks = 0; ks < 2; ks++) {
            const int ko = ks * 8;
            uint32_t af[4][4], bf[4][2];
#pragma unroll
            for (int mt = 0; mt < 4; mt++) {
                const int m0 = wm + mt * 16;
                af[mt][0] = f2tf32(As[(m0 + g    ) * ROWW + ko + tq]);
                af[mt][1] = f2tf32(As[(m0 + g + 8) * ROWW + ko + tq]);
                af[mt][2] = f2tf32(As[(m0 + g    ) * ROWW + ko + tq + 4]);
                af[mt][3] = f2tf32(As[(m0 + g + 8) * ROWW + ko + tq + 4]);
            }
#pragma unroll
            for (int nt = 0; nt < 4; nt++) {
                const int n0 = wn + nt * 8;
                bf[nt][0] = f2tf32(Bs[(n0 + g) * ROWW + ko + tq]);
                bf[nt][1] = f2tf32(Bs[(n0 + g) * ROWW + ko + tq + 4]);
            }
#pragma unroll
            for (int mt = 0; mt < 4; mt++)
#pragma unroll
                for (int nt = 0; nt < 4; nt++)
                    mma_tf32(acc[mt][nt], af[mt], bf[nt]);
        }
        buf = (buf + 1) % GSTAGES;
        __syncthreads();
    }

#pragma unroll
    for (int mt = 0; mt < 4; mt++) {
#pragma unroll
        for (int nt = 0; nt < 4; nt++) {
            const int row = bm + wm + mt * 16 + g;
            const int col = bn + wn + nt * 8 + 2 * tq;
            *(float2*)&C[(size_t)row * Nd + col]       = make_float2(acc[mt][nt][0], acc[mt][nt][1]);
            *(float2*)&C[(size_t)(row + 8) * Nd + col] = make_float2(acc[mt][nt][2], acc[mt][nt][3]);
        }
    }
}

// ---------------- Depthwise causal conv (K=4) + SiLU ----------------
__global__ void conv_silu_kernel(const float* __restrict__ conv_w, const float* __restrict__ conv_b)
{
    int idx = blockIdx.x * blockDim.x + threadIdx.x;
    if (idx >= LSEQ * DCONV) return;
    int t = idx / DCONV, c = idx % DCONV;
    float acc = conv_b[c];
    const float* w = conv_w + c * KCONV;
#pragma unroll
    for (int k = 0; k < KCONV; k++) {
        int tt = t + k - (KCONV - 1);
        if (tt >= 0) acc += w[k] * g_proj[(size_t)tt * DPROJ + DINTER + c];
    }
    g_xbc[idx] = fast_silu(acc);
}

// ---------------- dt softplus + per-chunk cumsum of A*dt ----------------
__global__ __launch_bounds__(CSZ) void dt_scan_kernel(
    const float* __restrict__ dt_bias, const float* __restrict__ A_log)
{
    int c = blockIdx.x, h = blockIdx.y, l = threadIdx.x;
    int t = c * CSZ + l;
    float raw = g_proj[(size_t)t * DPROJ + DINTER + DCONV + h] + dt_bias[h];
    float dtp = (raw > 0.f) ? (raw + log1pf(__expf(-raw))) : log1pf(__expf(raw));
    g_dt[t * NH + h] = dtp;
    float a = -__expf(A_log[h]) * dtp;

    __shared__ float s[CSZ];
    s[l] = a;
    __syncthreads();
#pragma unroll
    for (int off = 1; off < CSZ; off <<= 1) {
        float v = (l >= off) ? s[l - off] : 0.f;
        __syncthreads();
        s[l] += v;
        __syncthreads();
    }
    g_acs[(c * NH + h) * CSZ + l] = s[l];
    if (l == CSZ - 1) g_alast[c * NH + h] = s[l];
}

// ---------------- CBt[c][g][s][l] = sum_n C[l,n]*B[s,n] ----------------
__global__ __launch_bounds__(256) void cb_kernel()
{
    int c = blockIdx.x, g = blockIdx.y;
    int tid = threadIdx.x, tx = tid & 15, ty = tid >> 4;
    __shared__ float Csn[16][CSZ];
    __shared__ float Bsn[16][CSZ];
    float acc[8][8];
#pragma unroll
    for (int i = 0; i < 8; i++)
#pragma unroll
        for (int j = 0; j < 8; j++) acc[i][j] = 0.f;

    const float* Cg = g_xbc + DINTER + NG * DN + g * DN;
    const float* Bg = g_xbc + DINTER + g * DN;

    for (int n0 = 0; n0 < DN; n0 += 16) {
        for (int i = tid; i < CSZ * 4; i += 256) {
            int r = i >> 2, q = i & 3;
            const size_t row = (size_t)(c * CSZ + r) * DCONV + n0 + q * 4;
            float4 cv = *(const float4*)(Cg + row);
            float4 bv = *(const float4*)(Bg + row);
            Csn[q * 4 + 0][r] = cv.x; Csn[q * 4 + 1][r] = cv.y;
            Csn[q * 4 + 2][r] = cv.z; Csn[q * 4 + 3][r] = cv.w;
            Bsn[q * 4 + 0][r] = bv.x; Bsn[q * 4 + 1][r] = bv.y;
            Bsn[q * 4 + 2][r] = bv.z; Bsn[q * 4 + 3][r] = bv.w;
        }
        __syncthreads();
#pragma unroll
        for (int nn = 0; nn < 16; nn++) {
            float4 c0 = *(const float4*)&Csn[nn][tx * 8];
            float4 c1 = *(const float4*)&Csn[nn][tx * 8 + 4];
            float4 b0 = *(const float4*)&Bsn[nn][ty * 8];
            float4 b1 = *(const float4*)&Bsn[nn][ty * 8 + 4];
            float cl[8] = {c0.x, c0.y, c0.z, c0.w, c1.x, c1.y, c1.z, c1.w};
            float bs[8] = {b0.x, b0.y, b0.z, b0.w, b1.x, b1.y, b1.z, b1.w};
#pragma unroll
            for (int si = 0; si < 8; si++)
#pragma unroll
                for (int li = 0; li < 8; li++) acc[si][li] += cl[li] * bs[si];
        }
        __syncthreads();
    }
    float* out = g_cbt + (size_t)(c * NG + g) * CSZ * CSZ;
#pragma unroll
    for (int si = 0; si < 8; si++) {
        int s = ty * 8 + si;
        *(float4*)(out + (size_t)s * CSZ + tx * 8)     = make_float4(acc[si][0], acc[si][1], acc[si][2], acc[si][3]);
        *(float4*)(out + (size_t)s * CSZ + tx * 8 + 4) = make_float4(acc[si][4], acc[si][5], acc[si][6], acc[si][7]);
    }
}

// ---------------- Y_diag + D residual (decay matrix precomputed in smem tiles) ----------------
__global__ __launch_bounds__(256) void ydiag_kernel(const float* __restrict__ Dparam)
{
    int c = blockIdx.x, h = blockIdx.y, g = h >> 4;
    int tid = threadIdx.x, tx = tid & 15, ty = tid >> 4;
    __shared__ float xs[CSZ][DP];
    __shared__ float Ms[CSZ][17];
    __shared__ float acsS[CSZ];
    __shared__ float dts[CSZ];

    for (int i = tid; i < CSZ * DP / 4; i += 256) {
        int r = i >> 4, q = i & 15;
        *(float4*)&xs[r][q * 4] =
            *(const float4*)(g_xbc + (size_t)(c * CSZ + r) * DCONV + h * DP + q * 4);
    }
    if (tid < CSZ) {
        dts[tid]  = g_dt[(c * CSZ + tid) * NH + h];
        acsS[tid] = g_acs[(c * NH + h) * CSZ + tid];
    }
    __syncthreads();

    float acc[8][4];
#pragma unroll
    for (int i = 0; i < 8; i++)
#pragma unroll
        for (int j = 0; j < 4; j++) acc[i][j] = 0.f;

    const float* cbBase = g_cbt + (size_t)(c * NG + g) * CSZ * CSZ;
    const int ss_row = tid >> 4;
    const int lg     = tid & 15;

    for (int s0 = 0; s0 < CSZ; s0 += 16) {
        {
            const int s = s0 + ss_row;
            const float as  = acsS[s];
            const float dsv = dts[s];
            const float* cbRow = cbBase + (size_t)s * CSZ;
#pragma unroll
            for (int k = 0; k < 8; k++) {
                const int l = lg * 8 + k;
                float f = 0.f;
                if (s <= l) f = cbRow[l] * __expf(acsS[l] - as) * dsv;
                Ms[l][ss_row] = f;
            }
        }
        __syncthreads();

#pragma unroll
        for (int ss = 0; ss < 16; ss++) {
            const int s = s0 + ss;
            float msv[8];
#pragma unroll
            for (int i = 0; i < 8; i++) msv[i] = Ms[ty * 8 + i][ss];
            float4 xv4 = *(const float4*)&xs[s][tx * 4];
#pragma unroll
            for (int i = 0; i < 8; i++) {
                acc[i][0] += msv[i] * xv4.x;
                acc[i][1] += msv[i] * xv4.y;
                acc[i][2] += msv[i] * xv4.z;
                acc[i][3] += msv[i] * xv4.w;
            }
        }
        __syncthreads();
    }

    const float dcoef = Dparam[h];
#pragma unroll
    for (int i = 0; i < 8; i++) {
        int l = ty * 8 + i;
        float4 xr = *(const float4*)&xs[l][tx * 4];
        float4 o = make_float4(acc[i][0] + dcoef * xr.x, acc[i][1] + dcoef * xr.y,
                               acc[i][2] + dcoef * xr.z, acc[i][3] + dcoef * xr.w);
        *(float4*)(g_y + (size_t)(c * CSZ + l) * DINTER + h * DP + tx * 4) = o;
    }
}

// ---------------- Local chunk states ----------------
__global__ __launch_bounds__(256) void states_kernel()
{
    int c = blockIdx.x, h = blockIdx.y, g = h >> 4;
    int tid = threadIdx.x, tx = tid & 15, ty = tid >> 4;
    __shared__ float Bsh[32][DN];
    __shared__ float xds[32][DP];
    __shared__ float dec[32];
    float acc[4][8];
#pragma unroll
    for (int i = 0; i < 4; i++)
#pragma unroll
        for (int j = 0; j < 8; j++) acc[i][j] = 0.f;

    const float al = g_alast[c * NH + h];
    for (int l0 = 0; l0 < CSZ; l0 += 32) {
        for (int i = tid; i < 32 * DN / 4; i += 256) {
            int r = i >> 5, q = i & 31;
            *(float4*)&Bsh[r][q * 4] = *(const float4*)(
                g_xbc + (size_t)(c * CSZ + l0 + r) * DCONV + DINTER + g * DN + q * 4);
        }
        for (int i = tid; i < 32 * DP / 4; i += 256) {
            int r = i >> 4, q = i & 15;
            int t = c * CSZ + l0 + r;
            float4 xv = *(const float4*)(g_xbc + (size_t)t * DCONV + h * DP + q * 4);
            float d = g_dt[t * NH + h];
            xv.x *= d; xv.y *= d; xv.z *= d; xv.w *= d;
            *(float4*)&xds[r][q * 4] = xv;
        }
        if (tid < 32) dec[tid] = __expf(al - g_acs[(c * NH + h) * CSZ + l0 + tid]);
        __syncthreads();
#pragma unroll 8
        for (int ll = 0; ll < 32; ll++) {
            float d = dec[ll];
            float4 b0 = *(const float4*)&Bsh[ll][tx * 8];
            float4 b1 = *(const float4*)&Bsh[ll][tx * 8 + 4];
            float bb[8] = {b0.x, b0.y, b0.z, b0.w, b1.x, b1.y, b1.z, b1.w};
            float4 xv = *(const float4*)&xds[ll][ty * 4];
            float xp[4] = {xv.x * d, xv.y * d, xv.z * d, xv.w * d};
#pragma unroll
            for (int pi = 0; pi < 4; pi++)
#pragma unroll
                for (int nj = 0; nj < 8; nj++) acc[pi][nj] += xp[pi] * bb[nj];
        }
        __syncthreads();
    }
    float* out = g_states + (size_t)(c * NH + h) * DP * DN;
#pragma unroll
    for (int pi = 0; pi < 4; pi++) {
        int p = ty * 4 + pi;
        *(float4*)(out + (size_t)p * DN + tx * 8)     = make_float4(acc[pi][0], acc[pi][1], acc[pi][2], acc[pi][3]);
        *(float4*)(out + (size_t)p * DN + tx * 8 + 4) = make_float4(acc[pi][4], acc[pi][5], acc[pi][6], acc[pi][7]);
    }
}

// ---------------- Inter-chunk scan ----------------
__global__ void prefix_kernel()
{
    int idx = blockIdx.x * blockDim.x + threadIdx.x;
    if (idx >= NH * DP * DN) return;
    int h = idx >> 13;
    float s = 0.f;
#pragma unroll
    for (int c = 0; c < NCH; c++) {
        size_t off = (size_t)c * NH * DP * DN + idx;
        g_prefix[off] = s;
        s = __expf(g_alast[c * NH + h]) * s + g_states[off];
    }
}

// ---------------- Y_off ----------------
__global__ __launch_bounds__(256) void yoff_kernel()
{
    int c = blockIdx.x, h = blockIdx.y, g = h >> 4;
    int tid = threadIdx.x, tx = tid & 15, ty = tid >> 4;
    __shared__ float Cs[CSZ][32];
    __shared__ float Pf[DP][33];
    __shared__ float acsS[CSZ];
    if (tid < CSZ) acsS[tid] = g_acs[(c * NH + h) * CSZ + tid];

    float acc[8][4];
#pragma unroll
    for (int i = 0; i < 8; i++)
#pragma unroll
        for (int j = 0; j < 4; j++) acc[i][j] = 0.f;

    for (int n0 = 0; n0 < DN; n0 += 32) {
        for (int i = tid; i < CSZ * 8; i += 256) {
            int r = i >> 3, q = i & 7;
            *(float4*)&Cs[r][q * 4] = *(const float4*)(
                g_xbc + (size_t)(c * CSZ + r) * DCONV + DINTER + NG * DN + g * DN + n0 + q * 4);
        }
        for (int i = tid; i < DP * 8; i += 256) {
            int r = i >> 3, q = i & 7;
            float4 v = *(const float4*)(
                g_prefix + ((size_t)(c * NH + h) * DP + r) * DN + n0 + q * 4);
            Pf[r][q * 4 + 0] = v.x; Pf[r][q * 4 + 1] = v.y;
            Pf[r][q * 4 + 2] = v.z; Pf[r][q * 4 + 3] = v.w;
        }
        __syncthreads();
#pragma unroll 8
        for (int nn = 0; nn < 32; nn++) {
            float cl[8], pv[4];
#pragma unroll
            for (int i = 0; i < 8; i++) cl[i] = Cs[ty * 8 + i][nn];
#pragma unroll
            for (int j = 0; j < 4; j++) pv[j] = Pf[tx * 4 + j][nn];
#pragma unroll
            for (int i = 0; i < 8; i++)
#pragma unroll
                for (int j = 0; j < 4; j++) acc[i][j] += cl[i] * pv[j];
        }
        __syncthreads();
    }
#pragma unroll
    for (int i = 0; i < 8; i++) {
        int l = ty * 8 + i;
        float e = __expf(acsS[l]);
        float* yp = g_y + (size_t)(c * CSZ + l) * DINTER + h * DP + tx * 4;
        float4 y = *(float4*)yp;
        y.x += e * acc[i][0]; y.y += e * acc[i][1];
        y.z += e * acc[i][2]; y.w += e * acc[i][3];
        *(float4*)yp = y;
    }
}

// ---------------- RMSNorm * norm_w * silu(gate) ----------------
__global__ __launch_bounds__(256) void rms_gate_kernel(const float* __restrict__ norm_w)
{
    int t = blockIdx.x, tid = threadIdx.x;
    const size_t base = (size_t)t * DINTER;
    float ss = 0.f;
    for (int i = tid; i < DINTER; i += 256) {
        float v = g_y[base + i];
        ss += v * v;
    }
    __shared__ float red[256];
    red[tid] = ss;
    __syncthreads();
#pragma unroll
    for (int o = 128; o > 0; o >>= 1) {
        if (tid < o) red[tid] += red[tid + o];
        __syncthreads();
    }
    float inv = rsqrtf(red[0] / (float)DINTER + RMS_EPS);
    for (int i = tid; i < DINTER; i += 256) {
        float v = g_y[base + i] * inv * norm_w[i];
        v *= fast_silu(g_proj[(size_t)t * DPROJ + i]);
        g_y[base + i] = v;
    }
}

// ---------------- Launch ----------------
extern "C" void kernel_launch(void* const* d_in, const int* in_sizes, int n_in,
                              void* d_out, int out_size)
{
    (void)in_sizes; (void)n_in; (void)out_size;
    const float* hs         = (const float*)d_in[0];
    const float* in_proj_w  = (const float*)d_in[1];
    const float* conv_w     = (const float*)d_in[2];
    const float* conv_b     = (const float*)d_in[3];
    const float* dt_bias    = (const float*)d_in[4];
    const float* A_log      = (const float*)d_in[5];
    const float* Dp         = (const float*)d_in[6];
    const float* norm_w     = (const float*)d_in[7];
    const float* out_proj_w = (const float*)d_in[8];
    float* out = (float*)d_out;

    void *p_proj = nullptr, *p_y = nullptr;
    cudaGetSymbolAddress(&p_proj, g_proj);
    cudaGetSymbolAddress(&p_y, g_y);

    cudaFuncSetAttribute(gemm_tf32_kernel, cudaFuncAttributeMaxDynamicSharedMemorySize, GEMM_DSMEM);

    // 1) in-proj GEMM (tf32 + cp.async pipeline)
    gemm_tf32_kernel<<<dim3(DPROJ / 128, LSEQ / 128), 256, GEMM_DSMEM>>>(hs, in_proj_w, (float*)p_proj, DPROJ, DMODEL);
    // 2) causal depthwise conv + silu
    conv_silu_kernel<<<(LSEQ * DCONV + 255) / 256, 256>>>(conv_w, conv_b);
    // 3) dt softplus + per-chunk cumsum of A*dt
    dt_scan_kernel<<<dim3(NCH, NH), CSZ>>>(dt_bias, A_log);
    // 4) C·B^T per (chunk, group)
    cb_kernel<<<dim3(NCH, NG), 256>>>();
    // 5) intra-chunk (diagonal) output + D residual
    ydiag_kernel<<<dim3(NCH, NH), 256>>>(Dp);
    // 6) local chunk states
    states_kernel<<<dim3(NCH, NH), 256>>>();
    // 7) inter-chunk state scan
    prefix_kernel<<<(NH * DP * DN + 255) / 256, 256>>>();
    // 8) off-diagonal output (adds into g_y)
    yoff_kernel<<<dim3(NCH, NH), 256>>>();
    // 9) gated RMSNorm (in place)
    rms_gate_kernel<<<LSEQ, 256>>>(norm_w);
    // 10) out-proj GEMM
    gemm_tf32_kernel<<<dim3(DMODEL / 128, LSEQ / 128), 256, GEMM_DSMEM>>>((const float*)p_y, out_proj_w, out, DMODEL, DINTER);
}